// round 1
// baseline (speedup 1.0000x reference)
#include <cuda_runtime.h>
#include <math_constants.h>

// EvenLayer min-sum check-node update.
//
// Structure proof (from reference _build_inf_mask):
//   v = repeat(arange(1200), 3); c = (v*3+k) % 600; order = lexsort((c, v)).
//   Within a variable, var*3+k (k=0..2) never crosses a multiple of 600
//   (var*3 mod 600 <= 597), so per-variable checks are already ascending and
//   the lexsort permutation is the IDENTITY. Hence check(e) = e % 600, and
//   the neighbor set of edge e is { (e%600) + 600*m : m=0..5 } \ {e}.
//
// Per (batch b, check c): load the 6 edge values, and for each edge i emit
//   sign(prod_{j!=i} v_j) * max( min_{j!=i} |v_j| - bias[e_i], 0 ).

#define N_VAR 1200
#define D_V   3
#define N_CHK 600
#define BATCH 8
#define E     (N_VAR * D_V)   // 3600
#define DEG   (E / N_CHK)     // 6 edges per check

__global__ __launch_bounds__(128)
void even_layer_kernel(const float* __restrict__ x,
                       const float* __restrict__ bias,
                       float* __restrict__ out)
{
    const int idx = blockIdx.x * blockDim.x + threadIdx.x;  // 0 .. BATCH*N_CHK-1
    if (idx >= BATCH * N_CHK) return;

    const int b = idx / N_CHK;
    const int c = idx - b * N_CHK;

    const float* __restrict__ xb = x + b * E + c;
    float* __restrict__ ob = out + b * E + c;

    float v[DEG];
#pragma unroll
    for (int m = 0; m < DEG; ++m)
        v[m] = xb[m * N_CHK];

#pragma unroll
    for (int i = 0; i < DEG; ++i) {
        float p  = 1.0f;
        float mn = CUDART_INF_F;
#pragma unroll
        for (int j = 0; j < DEG; ++j) {
            if (j != i) {
                p  = p * v[j];
                mn = fminf(mn, fabsf(v[j]));
            }
        }
        // sign() semantics incl. sign(0)=0, matching jnp.sign(prod(...))
        const float s = (p > 0.0f) ? 1.0f : ((p < 0.0f) ? -1.0f : 0.0f);
        const float r = fmaxf(mn - bias[c + N_CHK * i], 0.0f);
        ob[N_CHK * i] = s * r;
    }
}

extern "C" void kernel_launch(void* const* d_in, const int* in_sizes, int n_in,
                              void* d_out, int out_size)
{
    // metadata order: inputs [BATCH,E] f32, bias [1,E] f32, inf_mask [E,E] f32 (unused)
    const float* x    = (const float*)d_in[0];
    const float* bias = (const float*)d_in[1];
    float* out        = (float*)d_out;

    const int total   = BATCH * N_CHK;        // 4800
    const int threads = 128;
    const int blocks  = (total + threads - 1) / threads;  // 38
    even_layer_kernel<<<blocks, threads>>>(x, bias, out);
}